// round 6
// baseline (speedup 1.0000x reference)
#include <cuda_runtime.h>

#define KK    27
#define CH    64
#define CAPK  65536          // per-k entry capacity (expected ~8K)
#define EXT2  0.75f          // KP_EXTENT^2
#define INV_EXT 1.15470053837925f
#define TH2   (1.8675f * 1.8675f)
#define SLICES 11
#define PAD   68             // floats per xs row (64 + 4; 272B = 17*16, 16B-aligned)

// global scratch (static __device__ — no runtime allocation)
__device__ unsigned g_pack[KK * CAPK];   // q<<16 | ind
__device__ float    g_w[KK * CAPK];
__device__ int      g_cnt[KK];

// ---------------- packed f32x2 helpers -------------------------------------
#define PACK2(d, lo, hi) \
    asm("mov.b64 %0, {%1, %2};" : "=l"(d) : "r"(__float_as_uint(lo)), "r"(__float_as_uint(hi)))
#define FMA2(acc, a, b) \
    asm("fma.rn.f32x2 %0, %1, %2, %0;" : "+l"(acc) : "l"(a), "l"(b))
#define UNPACK2(lo, hi, v) \
    asm("mov.b64 {%0, %1}, %2;" : "=r"(lo), "=r"(hi) : "l"(v))

__device__ __forceinline__ void red_add_v4(float* p, float a, float b,
                                           float c, float d) {
    asm volatile("red.global.add.v4.f32 [%0], {%1, %2, %3, %4};"
                 :: "l"(p), "f"(a), "f"(b), "f"(c), "f"(d) : "memory");
}

__device__ __forceinline__ void cp16(float* dst_smem, const float* src) {
    unsigned d = (unsigned)__cvta_generic_to_shared(dst_smem);
    asm volatile("cp.async.cg.shared.global [%0], [%1], 16;"
                 :: "r"(d), "l"(src) : "memory");
}
#define CP_COMMIT() asm volatile("cp.async.commit_group;" ::: "memory")
#define CP_WAIT(n)  asm volatile("cp.async.wait_group %0;" :: "n"(n) : "memory")

// ---------------- kernel 0: zero out + counters ----------------------------
__global__ void zero_kernel(float* __restrict__ out, int n4) {
    int i = blockIdx.x * blockDim.x + threadIdx.x;
    if (i < n4) ((float4*)out)[i] = make_float4(0.f, 0.f, 0.f, 0.f);
    if (blockIdx.x == 0 && threadIdx.x < KK) g_cnt[threadIdx.x] = 0;
}

// ---------------- kernel 1: build per-k entry lists ------------------------
__global__ __launch_bounds__(256) void build_kernel(
    const float* __restrict__ q_pts,   // [N,3]
    const float* __restrict__ s_pts,   // [M,3]
    const int*   __restrict__ inds,    // [N,32]
    const float* __restrict__ x,       // [M,64]  (fallback only)
    const float* __restrict__ W,       // [27,64,64] (fallback only)
    const float* __restrict__ kpts,    // [27,3]
    float* __restrict__ out,           // fallback only
    int N, int M)
{
    int p = blockIdx.x * blockDim.x + threadIdx.x;
    if (p >= N * 32) return;
    int q = p >> 5;
    int ind = inds[p];
    if ((unsigned)ind >= (unsigned)M) return;        // shadow neighbor

    float qx = q_pts[q * 3 + 0], qy = q_pts[q * 3 + 1], qz = q_pts[q * 3 + 2];
    float dx = s_pts[ind * 3 + 0] - qx;
    float dy = s_pts[ind * 3 + 1] - qy;
    float dz = s_pts[ind * 3 + 2] - qz;
    if (dx * dx + dy * dy + dz * dz >= TH2) return;  // ~97% reject

    #pragma unroll 1
    for (int k = 0; k < KK; k++) {
        float ex = dx - kpts[k * 3 + 0];
        float ey = dy - kpts[k * 3 + 1];
        float ez = dz - kpts[k * 3 + 2];
        float dd = ex * ex + ey * ey + ez * ez;
        if (dd < EXT2) {
            float w = 1.f - sqrtf(dd) * INV_EXT;
            int pos = atomicAdd(&g_cnt[k], 1);
            if (pos < CAPK) {
                g_pack[k * CAPK + pos] = ((unsigned)q << 16) | (unsigned)ind;
                g_w[k * CAPK + pos]    = w;
            } else {
                // correctness fallback (statistically unreachable)
                const float* xr = x + (size_t)ind * CH;
                const float* wk = W + (size_t)k * CH * CH;
                for (int o = 0; o < CH; o++) {
                    float a = 0.f;
                    for (int c = 0; c < CH; c++) a += xr[c] * wk[c * CH + o];
                    atomicAdd(&out[(size_t)q * CH + o], w * a);
                }
            }
        }
    }
}

// ---------------- kernel 2: pipelined per-k GEMM + scatter -----------------
// grid (27, SLICES), 256 threads. Tile = 128 rows x 64 out, k-dim 64.
// Thread (rowsel = tid>>3 in 0..31, cg = tid&7): rows {rowsel+32*rr}, cols 8cg..8cg+7.
__global__ __launch_bounds__(256, 2) void gemm_kernel(
    const float* __restrict__ W,       // [27,64,64]
    const float* __restrict__ x,       // [M,64]
    float* __restrict__ out)           // [N,64]
{
    extern __shared__ float smem[];
    float* Ws  = smem;                       // 4096 floats
    float* xsA = Ws + CH * CH;               // 128*PAD
    float* xsB = xsA + 128 * PAD;            // 128*PAD
    int*   qs  = (int*)(xsB + 128 * PAD);    // 2*128
    float* sws = (float*)(qs + 256);         // 2*128

    const int k      = blockIdx.x;
    const int tid    = threadIdx.x;
    const int rowsel = tid >> 3;    // 0..31
    const int cg     = tid & 7;     // 0..7
    const int rowi   = tid >> 1;    // 0..127 (fetch row)
    const int half   = tid & 1;     // 0/1 (fetch half-row, 128B each)

    const int R = min(g_cnt[k], CAPK);
    if (R == 0) return;
    const int ntiles = (R + 127) >> 7;
    int t = blockIdx.y;
    if (t >= ntiles) return;

    // stage W[k] once
    {
        const float4* src = (const float4*)(W + (size_t)k * CH * CH);
        for (int i = tid; i < (CH * CH) / 4; i += 256) ((float4*)Ws)[i] = src[i];
    }

    // async fetch of tile tt into buffer p
    auto fetch = [&](int tt, int p) {
        int base = tt << 7;
        bool val = (base + rowi) < R;
        unsigned pk = val ? g_pack[k * CAPK + base + rowi] : 0u;
        if (half == 0) {
            qs[p * 128 + rowi]  = (int)(pk >> 16);
            sws[p * 128 + rowi] = val ? g_w[k * CAPK + base + rowi] : 0.f;
        }
        const float* src = x + (size_t)(pk & 0xFFFFu) * CH + half * 32;
        float* dst = (p ? xsB : xsA) + rowi * PAD + half * 32;
        #pragma unroll
        for (int j = 0; j < 8; j++) cp16(dst + 4 * j, src + 4 * j);
        CP_COMMIT();
    };

    fetch(t, 0);
    int pb = 0;

    for (; t < ntiles; t += SLICES) {
        int nxt = t + SLICES;
        bool hn = nxt < ntiles;
        if (hn) { fetch(nxt, pb ^ 1); CP_WAIT(1); }
        else    { CP_WAIT(0); }
        __syncthreads();   // all threads' cp.async data + qs/sws visible

        const float* xb = pb ? xsB : xsA;

        unsigned long long acc[4][4];
        #pragma unroll
        for (int a = 0; a < 4; a++)
            #pragma unroll
            for (int b = 0; b < 4; b++) acc[a][b] = 0ull;

        #pragma unroll 8
        for (int cin = 0; cin < CH; cin++) {
            float x0 = xb[(rowsel     ) * PAD + cin];
            float x1 = xb[(rowsel + 32) * PAD + cin];
            float x2 = xb[(rowsel + 64) * PAD + cin];
            float x3 = xb[(rowsel + 96) * PAD + cin];
            const float* wr = Ws + cin * CH + 8 * cg;
            unsigned long long w0 = *(const unsigned long long*)(wr);
            unsigned long long w1 = *(const unsigned long long*)(wr + 2);
            unsigned long long w2 = *(const unsigned long long*)(wr + 4);
            unsigned long long w3 = *(const unsigned long long*)(wr + 6);
            unsigned long long px;
            PACK2(px, x0, x0);
            FMA2(acc[0][0], px, w0); FMA2(acc[0][1], px, w1);
            FMA2(acc[0][2], px, w2); FMA2(acc[0][3], px, w3);
            PACK2(px, x1, x1);
            FMA2(acc[1][0], px, w0); FMA2(acc[1][1], px, w1);
            FMA2(acc[1][2], px, w2); FMA2(acc[1][3], px, w3);
            PACK2(px, x2, x2);
            FMA2(acc[2][0], px, w0); FMA2(acc[2][1], px, w1);
            FMA2(acc[2][2], px, w2); FMA2(acc[2][3], px, w3);
            PACK2(px, x3, x3);
            FMA2(acc[3][0], px, w0); FMA2(acc[3][1], px, w1);
            FMA2(acc[3][2], px, w2); FMA2(acc[3][3], px, w3);
        }

        // epilogue: scale by wt (folded out of the tile) + v4 reductions
        int base = t << 7;
        #pragma unroll
        for (int rr = 0; rr < 4; rr++) {
            int row = rowsel + 32 * rr;
            if (base + row < R) {
                float wt = sws[pb * 128 + row];
                float* op = out + (size_t)qs[pb * 128 + row] * CH + 8 * cg;
                unsigned a0, a1, a2, a3, b0, b1, b2, b3;
                UNPACK2(a0, a1, acc[rr][0]);
                UNPACK2(a2, a3, acc[rr][1]);
                UNPACK2(b0, b1, acc[rr][2]);
                UNPACK2(b2, b3, acc[rr][3]);
                red_add_v4(op,
                           wt * __uint_as_float(a0), wt * __uint_as_float(a1),
                           wt * __uint_as_float(a2), wt * __uint_as_float(a3));
                red_add_v4(op + 4,
                           wt * __uint_as_float(b0), wt * __uint_as_float(b1),
                           wt * __uint_as_float(b2), wt * __uint_as_float(b3));
            }
        }

        pb ^= 1;
        __syncthreads();   // everyone done reading xb/qs before overwriting
    }
}

// ---------------- launcher --------------------------------------------------
extern "C" void kernel_launch(void* const* d_in, const int* in_sizes, int n_in,
                              void* d_out, int out_size) {
    const float* q_pts = (const float*)d_in[0];
    const float* s_pts = (const float*)d_in[1];
    const int*   inds  = (const int*)d_in[2];
    const float* x     = (const float*)d_in[3];
    const float* W     = (const float*)d_in[4];
    const float* kpts  = (const float*)d_in[5];
    float*       out   = (float*)d_out;

    int N = in_sizes[0] / 3;
    int M = in_sizes[1] / 3;

    // 0) zero output + counters
    int n4 = out_size / 4;
    zero_kernel<<<(n4 + 255) / 256, 256>>>(out, n4);

    // 1) build per-k entry lists
    int pairs = N * 32;
    build_kernel<<<(pairs + 255) / 256, 256>>>(q_pts, s_pts, inds, x, W, kpts,
                                               out, N, M);

    // 2) pipelined per-k GEMM + scatter
    int smem = (CH * CH + 2 * 128 * PAD) * 4 + 256 * 4 + 256 * 4;  // 88064 B
    cudaFuncSetAttribute(gemm_kernel,
                         cudaFuncAttributeMaxDynamicSharedMemorySize, smem);
    dim3 grid(KK, SLICES);
    gemm_kernel<<<grid, 256, smem>>>(W, x, out);
}

// round 7
// speedup vs baseline: 1.0933x; 1.0933x over previous
#include <cuda_runtime.h>

#define KK    27
#define CH    64
#define CAPK  65536          // per-k entry capacity (expected ~8K)
#define EXT2  0.75f          // KP_EXTENT^2
#define INV_EXT 1.15470053837925f
#define TH2   (1.8675f * 1.8675f)
#define SLICES 22
#define PAD   68             // floats per xs row (272B, 16B-aligned)

// global scratch (static __device__ — no runtime allocation)
__device__ unsigned g_pack[KK * CAPK];   // q<<16 | ind
__device__ float    g_w[KK * CAPK];
__device__ int      g_cnt[KK];

// ---------------- packed f32x2 helpers -------------------------------------
#define PACK2(d, lo, hi) \
    asm("mov.b64 %0, {%1, %2};" : "=l"(d) : "r"(__float_as_uint(lo)), "r"(__float_as_uint(hi)))
#define FMA2(acc, a, b) \
    asm("fma.rn.f32x2 %0, %1, %2, %0;" : "+l"(acc) : "l"(a), "l"(b))
#define UNPACK2(lo, hi, v) \
    asm("mov.b64 {%0, %1}, %2;" : "=r"(lo), "=r"(hi) : "l"(v))

__device__ __forceinline__ void red_add_v4(float* p, float a, float b,
                                           float c, float d) {
    asm volatile("red.global.add.v4.f32 [%0], {%1, %2, %3, %4};"
                 :: "l"(p), "f"(a), "f"(b), "f"(c), "f"(d) : "memory");
}

__device__ __forceinline__ void cp8(float* dst_smem, const float* src) {
    unsigned d = (unsigned)__cvta_generic_to_shared(dst_smem);
    asm volatile("cp.async.ca.shared.global [%0], [%1], 8;"
                 :: "r"(d), "l"(src) : "memory");
}
#define CP_COMMIT() asm volatile("cp.async.commit_group;" ::: "memory")
#define CP_WAIT(n)  asm volatile("cp.async.wait_group %0;" :: "n"(n) : "memory")

// ---------------- kernel 0: zero out + counters ----------------------------
__global__ void zero_kernel(float* __restrict__ out, int n4) {
    int i = blockIdx.x * blockDim.x + threadIdx.x;
    if (i < n4) ((float4*)out)[i] = make_float4(0.f, 0.f, 0.f, 0.f);
    if (blockIdx.x == 0 && threadIdx.x < KK) g_cnt[threadIdx.x] = 0;
}

// ---------------- kernel 1: build per-k entry lists ------------------------
__global__ __launch_bounds__(256) void build_kernel(
    const float* __restrict__ q_pts,   // [N,3]
    const float* __restrict__ s_pts,   // [M,3]
    const int*   __restrict__ inds,    // [N,32]
    const float* __restrict__ x,       // [M,64]  (fallback only)
    const float* __restrict__ W,       // [27,64,64] (fallback only)
    const float* __restrict__ kpts,    // [27,3]
    float* __restrict__ out,           // fallback only
    int N, int M)
{
    int p = blockIdx.x * blockDim.x + threadIdx.x;
    if (p >= N * 32) return;
    int q = p >> 5;
    int ind = inds[p];
    if ((unsigned)ind >= (unsigned)M) return;        // shadow neighbor

    float qx = q_pts[q * 3 + 0], qy = q_pts[q * 3 + 1], qz = q_pts[q * 3 + 2];
    float dx = s_pts[ind * 3 + 0] - qx;
    float dy = s_pts[ind * 3 + 1] - qy;
    float dz = s_pts[ind * 3 + 2] - qz;
    if (dx * dx + dy * dy + dz * dz >= TH2) return;  // ~97% reject

    #pragma unroll 1
    for (int k = 0; k < KK; k++) {
        float ex = dx - kpts[k * 3 + 0];
        float ey = dy - kpts[k * 3 + 1];
        float ez = dz - kpts[k * 3 + 2];
        float dd = ex * ex + ey * ey + ez * ez;
        if (dd < EXT2) {
            float w = 1.f - sqrtf(dd) * INV_EXT;
            int pos = atomicAdd(&g_cnt[k], 1);
            if (pos < CAPK) {
                g_pack[k * CAPK + pos] = ((unsigned)q << 16) | (unsigned)ind;
                g_w[k * CAPK + pos]    = w;
            } else {
                // correctness fallback (statistically unreachable)
                const float* xr = x + (size_t)ind * CH;
                const float* wk = W + (size_t)k * CH * CH;
                for (int o = 0; o < CH; o++) {
                    float a = 0.f;
                    for (int c = 0; c < CH; c++) a += xr[c] * wk[c * CH + o];
                    atomicAdd(&out[(size_t)q * CH + o], w * a);
                }
            }
        }
    }
}

// ---------------- kernel 2: pipelined per-k GEMM + scatter -----------------
// grid (27, SLICES), 256 threads. Tile = 128 rows x 64 out, k-dim 64.
// Compute map: rowsel = tid>>3 (rows rowsel+{0,32,64,96}), cg = tid&7 (cols 8cg..+7).
// Fetch map: warp wid loads rows [wid*16, wid*16+16), 256B coalesced per row.
__global__ __launch_bounds__(256, 2) void gemm_kernel(
    const float* __restrict__ W,       // [27,64,64]
    const float* __restrict__ x,       // [M,64]
    float* __restrict__ out)           // [N,64]
{
    extern __shared__ float smem[];
    float* Ws  = smem;                       // 4096 floats
    float* xsA = Ws + CH * CH;               // 128*PAD
    float* xsB = xsA + 128 * PAD;            // 128*PAD
    int*   qs  = (int*)(xsB + 128 * PAD);    // 2*128
    float* sws = (float*)(qs + 256);         // 2*128

    const int k      = blockIdx.x;
    const int tid    = threadIdx.x;
    const int rowsel = tid >> 3;    // 0..31
    const int cg     = tid & 7;     // 0..7
    const int wid    = tid >> 5;    // 0..7
    const int lane   = tid & 31;

    const int R = min(g_cnt[k], CAPK);
    if (R == 0) return;
    const int ntiles = (R + 127) >> 7;
    int t = blockIdx.y;
    if (t >= ntiles) return;

    // stage W[k] once
    {
        const float4* src = (const float4*)(W + (size_t)k * CH * CH);
        for (int i = tid; i < (CH * CH) / 4; i += 256) ((float4*)Ws)[i] = src[i];
    }

    // async coalesced fetch of tile tt into buffer p
    auto fetch = [&](int tt, int p) {
        int base = tt << 7;
        float* dstb = (p ? xsB : xsA);
        #pragma unroll 4
        for (int i = 0; i < 16; i++) {
            int row = wid * 16 + i;
            int gi  = base + row;
            unsigned pk = (gi < R) ? g_pack[k * CAPK + gi] : 0u;  // warp-bcast
            const float* src = x + (size_t)(pk & 0xFFFFu) * CH + 2 * lane;
            cp8(dstb + row * PAD + 2 * lane, src);
        }
        if (lane < 16) {
            int row = wid * 16 + lane;
            int gi  = base + row;
            bool v  = gi < R;
            unsigned pk = v ? g_pack[k * CAPK + gi] : 0u;
            qs[p * 128 + row]  = (int)(pk >> 16);
            sws[p * 128 + row] = v ? g_w[k * CAPK + gi] : 0.f;
        }
        CP_COMMIT();
    };

    fetch(t, 0);
    int pb = 0;

    for (; t < ntiles; t += SLICES) {
        int nxt = t + SLICES;
        bool hn = nxt < ntiles;
        if (hn) { fetch(nxt, pb ^ 1); CP_WAIT(1); }
        else    { CP_WAIT(0); }
        __syncthreads();   // cp.async data + qs/sws visible to all

        const float* xb = pb ? xsB : xsA;

        unsigned long long acc[4][4];
        #pragma unroll
        for (int a = 0; a < 4; a++)
            #pragma unroll
            for (int b = 0; b < 4; b++) acc[a][b] = 0ull;

        #pragma unroll 8
        for (int cin = 0; cin < CH; cin++) {
            float x0 = xb[(rowsel     ) * PAD + cin];   // 4 bcast LDS, 4 banks
            float x1 = xb[(rowsel + 32) * PAD + cin];
            float x2 = xb[(rowsel + 64) * PAD + cin];
            float x3 = xb[(rowsel + 96) * PAD + cin];
            // W pairs loaded pre-packed: 2x LDS.128, contiguous 128B/warp
            const ulonglong2* wp =
                (const ulonglong2*)(Ws + cin * CH + 8 * cg);
            ulonglong2 wv0 = wp[0];
            ulonglong2 wv1 = wp[1];
            unsigned long long px;
            PACK2(px, x0, x0);
            FMA2(acc[0][0], px, wv0.x); FMA2(acc[0][1], px, wv0.y);
            FMA2(acc[0][2], px, wv1.x); FMA2(acc[0][3], px, wv1.y);
            PACK2(px, x1, x1);
            FMA2(acc[1][0], px, wv0.x); FMA2(acc[1][1], px, wv0.y);
            FMA2(acc[1][2], px, wv1.x); FMA2(acc[1][3], px, wv1.y);
            PACK2(px, x2, x2);
            FMA2(acc[2][0], px, wv0.x); FMA2(acc[2][1], px, wv0.y);
            FMA2(acc[2][2], px, wv1.x); FMA2(acc[2][3], px, wv1.y);
            PACK2(px, x3, x3);
            FMA2(acc[3][0], px, wv0.x); FMA2(acc[3][1], px, wv0.y);
            FMA2(acc[3][2], px, wv1.x); FMA2(acc[3][3], px, wv1.y);
        }

        // epilogue: scale by wt (folded out of the tile) + v4 reductions
        int base = t << 7;
        #pragma unroll
        for (int rr = 0; rr < 4; rr++) {
            int row = rowsel + 32 * rr;
            if (base + row < R) {
                float wt = sws[pb * 128 + row];
                float* op = out + (size_t)qs[pb * 128 + row] * CH + 8 * cg;
                unsigned a0, a1, a2, a3, b0, b1, b2, b3;
                UNPACK2(a0, a1, acc[rr][0]);
                UNPACK2(a2, a3, acc[rr][1]);
                UNPACK2(b0, b1, acc[rr][2]);
                UNPACK2(b2, b3, acc[rr][3]);
                red_add_v4(op,
                           wt * __uint_as_float(a0), wt * __uint_as_float(a1),
                           wt * __uint_as_float(a2), wt * __uint_as_float(a3));
                red_add_v4(op + 4,
                           wt * __uint_as_float(b0), wt * __uint_as_float(b1),
                           wt * __uint_as_float(b2), wt * __uint_as_float(b3));
            }
        }

        pb ^= 1;
        __syncthreads();   // all reads of xb/qs done before next overwrite
    }
}

// ---------------- launcher --------------------------------------------------
extern "C" void kernel_launch(void* const* d_in, const int* in_sizes, int n_in,
                              void* d_out, int out_size) {
    const float* q_pts = (const float*)d_in[0];
    const float* s_pts = (const float*)d_in[1];
    const int*   inds  = (const int*)d_in[2];
    const float* x     = (const float*)d_in[3];
    const float* W     = (const float*)d_in[4];
    const float* kpts  = (const float*)d_in[5];
    float*       out   = (float*)d_out;

    int N = in_sizes[0] / 3;
    int M = in_sizes[1] / 3;

    // 0) zero output + counters
    int n4 = out_size / 4;
    zero_kernel<<<(n4 + 255) / 256, 256>>>(out, n4);

    // 1) build per-k entry lists
    int pairs = N * 32;
    build_kernel<<<(pairs + 255) / 256, 256>>>(q_pts, s_pts, inds, x, W, kpts,
                                               out, N, M);

    // 2) pipelined per-k GEMM + scatter
    int smem = (CH * CH + 2 * 128 * PAD) * 4 + 256 * 4 + 256 * 4;  // 88064 B
    cudaFuncSetAttribute(gemm_kernel,
                         cudaFuncAttributeMaxDynamicSharedMemorySize, smem);
    dim3 grid(KK, SLICES);
    gemm_kernel<<<grid, 256, smem>>>(W, x, out);
}

// round 8
// speedup vs baseline: 1.9129x; 1.7496x over previous
#include <cuda_runtime.h>

#define KK    27
#define CH    64
#define CAPK  65536          // per-k entry capacity (expected ~8K)
#define EXT2  0.75f          // KP_EXTENT^2
#define INV_EXT 1.15470053837925f
#define TH2   (1.8675f * 1.8675f)
#define SLICES 22
#define PAD   68             // floats per xs row (272B, 16B-aligned)
#define CNT_STRIDE 64        // 256B between counters -> distinct L2 slices

// global scratch (static __device__ — no runtime allocation)
__device__ unsigned g_pack[KK * CAPK];   // q<<16 | ind
__device__ float    g_w[KK * CAPK];
__device__ int      g_cnt[KK * CNT_STRIDE];

// ---------------- packed f32x2 helpers -------------------------------------
#define PACK2(d, lo, hi) \
    asm("mov.b64 %0, {%1, %2};" : "=l"(d) : "r"(__float_as_uint(lo)), "r"(__float_as_uint(hi)))
#define FMA2(acc, a, b) \
    asm("fma.rn.f32x2 %0, %1, %2, %0;" : "+l"(acc) : "l"(a), "l"(b))
#define UNPACK2(lo, hi, v) \
    asm("mov.b64 {%0, %1}, %2;" : "=r"(lo), "=r"(hi) : "l"(v))

__device__ __forceinline__ void red_add_v4(float* p, float a, float b,
                                           float c, float d) {
    asm volatile("red.global.add.v4.f32 [%0], {%1, %2, %3, %4};"
                 :: "l"(p), "f"(a), "f"(b), "f"(c), "f"(d) : "memory");
}

__device__ __forceinline__ void cp8(float* dst_smem, const float* src) {
    unsigned d = (unsigned)__cvta_generic_to_shared(dst_smem);
    asm volatile("cp.async.ca.shared.global [%0], [%1], 8;"
                 :: "r"(d), "l"(src) : "memory");
}
#define CP_COMMIT() asm volatile("cp.async.commit_group;" ::: "memory")
#define CP_WAIT(n)  asm volatile("cp.async.wait_group %0;" :: "n"(n) : "memory")

// ---------------- kernel 0: zero out + counters ----------------------------
__global__ void zero_kernel(float* __restrict__ out, int n4) {
    int i = blockIdx.x * blockDim.x + threadIdx.x;
    if (i < n4) ((float4*)out)[i] = make_float4(0.f, 0.f, 0.f, 0.f);
    if (blockIdx.x == 0 && threadIdx.x < KK)
        g_cnt[threadIdx.x * CNT_STRIDE] = 0;
}

// ---------------- kernel 1: build per-k entry lists (ballot-compacted) -----
// One warp = one query's 32 neighbors. Survivors broadcast via shfl; then
// lane = kernel-point index evaluates all 27 k in parallel.
__global__ __launch_bounds__(256) void build_kernel(
    const float* __restrict__ q_pts,   // [N,3]
    const float* __restrict__ s_pts,   // [M,3]
    const int*   __restrict__ inds,    // [N,32]
    const float* __restrict__ x,       // [M,64]  (fallback only)
    const float* __restrict__ W,       // [27,64,64] (fallback only)
    const float* __restrict__ kpts,    // [27,3]
    float* __restrict__ out,           // fallback only
    int N, int M)
{
    const int tid  = threadIdx.x;
    const int lane = tid & 31;
    const int p    = blockIdx.x * 256 + tid;
    const int q    = p >> 5;                 // warp-uniform

    // per-lane kernel point (lane < 27)
    float kx = 0.f, ky = 0.f, kz = 0.f;
    if (lane < KK) {
        kx = kpts[lane * 3 + 0];
        ky = kpts[lane * 3 + 1];
        kz = kpts[lane * 3 + 2];
    }

    bool  alive = false;
    float dx = 0.f, dy = 0.f, dz = 0.f;
    int   ind = 0;
    if (p < N * 32) {
        ind = inds[p];
        if ((unsigned)ind < (unsigned)M) {
            float qx = q_pts[q * 3 + 0];
            float qy = q_pts[q * 3 + 1];
            float qz = q_pts[q * 3 + 2];
            dx = s_pts[ind * 3 + 0] - qx;
            dy = s_pts[ind * 3 + 1] - qy;
            dz = s_pts[ind * 3 + 2] - qz;
            alive = (dx * dx + dy * dy + dz * dz) < TH2;   // ~97% reject
        }
    }

    unsigned mask = __ballot_sync(0xFFFFFFFFu, alive);
    while (mask) {
        int src = __ffs(mask) - 1;
        mask &= mask - 1;
        float sdx = __shfl_sync(0xFFFFFFFFu, dx, src);
        float sdy = __shfl_sync(0xFFFFFFFFu, dy, src);
        float sdz = __shfl_sync(0xFFFFFFFFu, dz, src);
        int   sind = __shfl_sync(0xFFFFFFFFu, ind, src);

        float ex = sdx - kx, ey = sdy - ky, ez = sdz - kz;
        float dd = ex * ex + ey * ey + ez * ez;
        if (lane < KK && dd < EXT2) {
            float w = 1.f - sqrtf(dd) * INV_EXT;
            int pos = atomicAdd(&g_cnt[lane * CNT_STRIDE], 1);
            if (pos < CAPK) {
                g_pack[lane * CAPK + pos] =
                    ((unsigned)q << 16) | (unsigned)sind;
                g_w[lane * CAPK + pos] = w;
            } else {
                // correctness fallback (statistically unreachable)
                const float* xr = x + (size_t)sind * CH;
                const float* wk = W + (size_t)lane * CH * CH;
                for (int o = 0; o < CH; o++) {
                    float a = 0.f;
                    for (int c = 0; c < CH; c++) a += xr[c] * wk[c * CH + o];
                    atomicAdd(&out[(size_t)q * CH + o], w * a);
                }
            }
        }
    }
}

// ---------------- kernel 2: pipelined per-k GEMM + scatter -----------------
// grid (27, SLICES), 256 threads. Tile = 128 rows x 64 out, k-dim 64.
// Compute map: rowsel = tid>>3 (rows rowsel+{0,32,64,96}), cg = tid&7 (cols 8cg..+7).
// Fetch map: warp wid loads rows [wid*16, wid*16+16), 256B coalesced per row.
__global__ __launch_bounds__(256, 2) void gemm_kernel(
    const float* __restrict__ W,       // [27,64,64]
    const float* __restrict__ x,       // [M,64]
    float* __restrict__ out)           // [N,64]
{
    extern __shared__ float smem[];
    float* Ws  = smem;                       // 4096 floats
    float* xsA = Ws + CH * CH;               // 128*PAD
    float* xsB = xsA + 128 * PAD;            // 128*PAD
    int*   qs  = (int*)(xsB + 128 * PAD);    // 2*128
    float* sws = (float*)(qs + 256);         // 2*128

    const int k      = blockIdx.x;
    const int tid    = threadIdx.x;
    const int rowsel = tid >> 3;    // 0..31
    const int cg     = tid & 7;     // 0..7
    const int wid    = tid >> 5;    // 0..7
    const int lane   = tid & 31;

    const int R = min(g_cnt[k * CNT_STRIDE], CAPK);
    if (R == 0) return;
    const int ntiles = (R + 127) >> 7;
    int t = blockIdx.y;
    if (t >= ntiles) return;

    // stage W[k] once
    {
        const float4* src = (const float4*)(W + (size_t)k * CH * CH);
        for (int i = tid; i < (CH * CH) / 4; i += 256) ((float4*)Ws)[i] = src[i];
    }

    // async coalesced fetch of tile tt into buffer p
    auto fetch = [&](int tt, int p) {
        int base = tt << 7;
        float* dstb = (p ? xsB : xsA);
        #pragma unroll 4
        for (int i = 0; i < 16; i++) {
            int row = wid * 16 + i;
            int gi  = base + row;
            unsigned pk = (gi < R) ? g_pack[k * CAPK + gi] : 0u;  // warp-bcast
            const float* src = x + (size_t)(pk & 0xFFFFu) * CH + 2 * lane;
            cp8(dstb + row * PAD + 2 * lane, src);
        }
        if (lane < 16) {
            int row = wid * 16 + lane;
            int gi  = base + row;
            bool v  = gi < R;
            unsigned pk = v ? g_pack[k * CAPK + gi] : 0u;
            qs[p * 128 + row]  = (int)(pk >> 16);
            sws[p * 128 + row] = v ? g_w[k * CAPK + gi] : 0.f;
        }
        CP_COMMIT();
    };

    fetch(t, 0);
    int pb = 0;

    for (; t < ntiles; t += SLICES) {
        int nxt = t + SLICES;
        bool hn = nxt < ntiles;
        if (hn) { fetch(nxt, pb ^ 1); CP_WAIT(1); }
        else    { CP_WAIT(0); }
        __syncthreads();   // cp.async data + qs/sws visible to all

        const float* xb = pb ? xsB : xsA;

        unsigned long long acc[4][4];
        #pragma unroll
        for (int a = 0; a < 4; a++)
            #pragma unroll
            for (int b = 0; b < 4; b++) acc[a][b] = 0ull;

        #pragma unroll 4
        for (int cin4 = 0; cin4 < 16; cin4++) {
            // 4 broadcast LDS.128: x values for 4 rows x 4 cin
            float4 xv0 = *(const float4*)&xb[(rowsel     ) * PAD + 4 * cin4];
            float4 xv1 = *(const float4*)&xb[(rowsel + 32) * PAD + 4 * cin4];
            float4 xv2 = *(const float4*)&xb[(rowsel + 64) * PAD + 4 * cin4];
            float4 xv3 = *(const float4*)&xb[(rowsel + 96) * PAD + 4 * cin4];
            const float* f0 = (const float*)&xv0;
            const float* f1 = (const float*)&xv1;
            const float* f2 = (const float*)&xv2;
            const float* f3 = (const float*)&xv3;
            #pragma unroll
            for (int j = 0; j < 4; j++) {
                int cin = 4 * cin4 + j;
                const ulonglong2* wp =
                    (const ulonglong2*)(Ws + cin * CH + 8 * cg);
                ulonglong2 wv0 = wp[0];
                ulonglong2 wv1 = wp[1];
                unsigned long long px;
                PACK2(px, f0[j], f0[j]);
                FMA2(acc[0][0], px, wv0.x); FMA2(acc[0][1], px, wv0.y);
                FMA2(acc[0][2], px, wv1.x); FMA2(acc[0][3], px, wv1.y);
                PACK2(px, f1[j], f1[j]);
                FMA2(acc[1][0], px, wv0.x); FMA2(acc[1][1], px, wv0.y);
                FMA2(acc[1][2], px, wv1.x); FMA2(acc[1][3], px, wv1.y);
                PACK2(px, f2[j], f2[j]);
                FMA2(acc[2][0], px, wv0.x); FMA2(acc[2][1], px, wv0.y);
                FMA2(acc[2][2], px, wv1.x); FMA2(acc[2][3], px, wv1.y);
                PACK2(px, f3[j], f3[j]);
                FMA2(acc[3][0], px, wv0.x); FMA2(acc[3][1], px, wv0.y);
                FMA2(acc[3][2], px, wv1.x); FMA2(acc[3][3], px, wv1.y);
            }
        }

        // epilogue: scale by wt (folded out of the tile) + v4 reductions
        int base = t << 7;
        #pragma unroll
        for (int rr = 0; rr < 4; rr++) {
            int row = rowsel + 32 * rr;
            if (base + row < R) {
                float wt = sws[pb * 128 + row];
                float* op = out + (size_t)qs[pb * 128 + row] * CH + 8 * cg;
                unsigned a0, a1, a2, a3, b0, b1, b2, b3;
                UNPACK2(a0, a1, acc[rr][0]);
                UNPACK2(a2, a3, acc[rr][1]);
                UNPACK2(b0, b1, acc[rr][2]);
                UNPACK2(b2, b3, acc[rr][3]);
                red_add_v4(op,
                           wt * __uint_as_float(a0), wt * __uint_as_float(a1),
                           wt * __uint_as_float(a2), wt * __uint_as_float(a3));
                red_add_v4(op + 4,
                           wt * __uint_as_float(b0), wt * __uint_as_float(b1),
                           wt * __uint_as_float(b2), wt * __uint_as_float(b3));
            }
        }

        pb ^= 1;
        __syncthreads();   // all reads of xb/qs done before next overwrite
    }
}

// ---------------- launcher --------------------------------------------------
extern "C" void kernel_launch(void* const* d_in, const int* in_sizes, int n_in,
                              void* d_out, int out_size) {
    const float* q_pts = (const float*)d_in[0];
    const float* s_pts = (const float*)d_in[1];
    const int*   inds  = (const int*)d_in[2];
    const float* x     = (const float*)d_in[3];
    const float* W     = (const float*)d_in[4];
    const float* kpts  = (const float*)d_in[5];
    float*       out   = (float*)d_out;

    int N = in_sizes[0] / 3;
    int M = in_sizes[1] / 3;

    // 0) zero output + counters
    int n4 = out_size / 4;
    zero_kernel<<<(n4 + 255) / 256, 256>>>(out, n4);

    // 1) build per-k entry lists (ballot-compacted)
    int pairs = N * 32;
    build_kernel<<<(pairs + 255) / 256, 256>>>(q_pts, s_pts, inds, x, W, kpts,
                                               out, N, M);

    // 2) pipelined per-k GEMM + scatter
    int smem = (CH * CH + 2 * 128 * PAD) * 4 + 256 * 4 + 256 * 4;  // 88064 B
    cudaFuncSetAttribute(gemm_kernel,
                         cudaFuncAttributeMaxDynamicSharedMemorySize, smem);
    dim3 grid(KK, SLICES);
    gemm_kernel<<<grid, 256, smem>>>(W, x, out);
}